// round 4
// baseline (speedup 1.0000x reference)
#include <cuda_runtime.h>
#include <math.h>

#define Bn 64
#define Cn 3
#define Hn 512
#define Wn 512
#define HW (Hn * Wn)
#define CUT_H 256
#define CUT_W 256

#define TILE 32            // output tile per block (32x32)
#define SBW 61             // smem tile stride (odd, anti-conflict)
#define SBH 60             // max staged rows
#define SCH (SBH * SBW)    // floats per channel

struct __align__(16) BatchParams {
    float m00, m01, m10, m11;
    float tx, ty;
    float bb, cc, ss;
    int   flip, cut, y0, x0;
    int   vec, pad0, pad1, pad2;
};

__device__ BatchParams g_params[Bn];

__global__ void precompute_params_kernel(
    const float* __restrict__ u_angle, const float* __restrict__ u_scale,
    const float* __restrict__ u_trans, const float* __restrict__ u_bright,
    const float* __restrict__ u_contrast, const float* __restrict__ u_sat,
    const int* __restrict__ m_flip, const int* __restrict__ m_rot,
    const int* __restrict__ m_scale, const int* __restrict__ m_trans,
    const int* __restrict__ m_bright, const int* __restrict__ m_contrast,
    const int* __restrict__ m_sat, const int* __restrict__ m_cut,
    const int* __restrict__ y0, const int* __restrict__ x0)
{
    int b = threadIdx.x;
    if (b >= Bn) return;
    const float PI = 3.14159265358979323846f;
    float angle = (m_rot[b] > 0) ? (u_angle[b] * 2.0f - 1.0f) * PI : 0.0f;
    float sc    = (m_scale[b] > 0) ? (u_scale[b] * 2.0f - 1.0f) * 0.2f + 1.0f : 1.0f;
    float tr    = (m_trans[b] > 0) ? (u_trans[b] * 2.0f - 1.0f) * 0.125f : 0.0f;
    float ca = cosf(angle);
    float sa = sinf(angle);
    BatchParams p;
    p.m00 = sc * ca;  p.m01 = -sc * sa;
    p.m10 = sc * sa;  p.m11 =  sc * ca;
    p.tx = tr; p.ty = tr;
    p.bb = (m_bright[b]   > 0) ? u_bright[b] * 0.2f   : 0.0f;
    p.cc = (m_contrast[b] > 0) ? u_contrast[b] + 0.5f : 1.0f;
    p.ss = (m_sat[b]      > 0) ? u_sat[b] * 2.0f      : 1.0f;
    p.flip = m_flip[b];
    p.cut  = m_cut[b];
    p.y0 = y0[b];
    p.x0 = x0[b];
    p.vec = (m_rot[b] > 0) ? 1 : 0;
    g_params[b] = p;
}

__device__ __forceinline__ float reflect_coord(float v, float size) {
    v = fabsf(v + 0.5f);
    v = fmodf(v, 2.0f * size);
    v = fminf(v, 2.0f * size - v);
    return fminf(fmaxf(v - 0.5f, 0.0f), size - 1.0f);
}

__device__ __forceinline__ float clip1(float v) {
    return fminf(fmaxf(v, -1.0f), 1.0f);
}

__device__ __forceinline__ void color_and_store(
    float r0, float r1, float r2, const BatchParams& p,
    float* __restrict__ out, size_t out_idx)
{
    r0 = clip1(clip1(r0 + p.bb) * p.cc);
    r1 = clip1(clip1(r1 + p.bb) * p.cc);
    r2 = clip1(clip1(r2 + p.bb) * p.cc);
    const float gray = (r0 + r1 + r2) * (1.0f / 3.0f);
    r0 = clip1(gray + p.ss * (r0 - gray));
    r1 = clip1(gray + p.ss * (r1 - gray));
    r2 = clip1(gray + p.ss * (r2 - gray));
    out[out_idx]          = r0;
    out[out_idx + HW]     = r1;
    out[out_idx + 2 * HW] = r2;
}

__global__ void __launch_bounds__(256) augment_kernel(
    const float* __restrict__ images,
    const float* __restrict__ noise,
    float* __restrict__ out)
{
    __shared__ float s_img[Cn * SCH];

    const int b = blockIdx.y;
    const BatchParams p = g_params[b];

    const int bx  = blockIdx.x & 15;
    const int by  = blockIdx.x >> 4;
    const int tx0 = bx * TILE;
    const int ty0 = by * TILE;

    const int tid  = threadIdx.x;
    const int warp = tid >> 5;
    const int lane = tid & 31;

    const size_t img_base = (size_t)b * (Cn * HW);

    // ---- full-cut tile: pure noise copy ----
    if (p.cut > 0 &&
        tx0 >= p.x0 && tx0 + TILE <= p.x0 + CUT_W &&
        ty0 >= p.y0 && ty0 + TILE <= p.y0 + CUT_H) {
        #pragma unroll
        for (int k = 0; k < 4; k++) {
            const int y = ty0 + 8 * k + (tid >> 5);
            const int x = tx0 + lane;
            const size_t oi = img_base + (size_t)y * Wn + x;
            out[oi]          = noise[oi];
            out[oi + HW]     = noise[oi + HW];
            out[oi + 2 * HW] = noise[oi + 2 * HW];
        }
        return;
    }

    // Affine in pixel coords (flipped-image space when p.flip):
    // fx = Ax*x + Bx*y + Cx ; fy = Ay*x + By*y + Cy
    const float S = 512.0f / 511.0f;
    const float Ax = p.m00 * S, Bx = p.m01 * S;
    const float Cx = (p.tx - p.m00 - p.m01) * 256.0f + 255.5f;
    const float Ay = p.m10 * S, By = p.m11 * S;
    const float Cy = (p.ty - p.m10 - p.m11) * 256.0f + 255.5f;

    // ---- path selection (block-uniform) ----
    int path = 0;            // 0 = scalar row-major, 1 = smem staged, 2 = scalar 16x2
    int xs0 = 0, ys0 = 0, bwid = 0, bhei = 0;
    if (p.vec) {
        const float x0a = (float)tx0, x0b = (float)(tx0 + TILE - 1);
        const float y0a = (float)ty0, y0b = (float)(ty0 + TILE - 1);
        const float fxmin = fminf(Ax * x0a, Ax * x0b) + fminf(Bx * y0a, Bx * y0b) + Cx - 0.01f;
        const float fxmax = fmaxf(Ax * x0a, Ax * x0b) + fmaxf(Bx * y0a, Bx * y0b) + Cx + 0.01f;
        const float fymin = fminf(Ay * x0a, Ay * x0b) + fminf(By * y0a, By * y0b) + Cy - 0.01f;
        const float fymax = fmaxf(Ay * x0a, Ay * x0b) + fmaxf(By * y0a, By * y0b) + Cy + 0.01f;
        if (fxmin >= 0.0f && fxmax < 511.0f && fymin >= 0.0f && fymax < 511.0f) {
            xs0 = (int)floorf(fxmin);
            ys0 = (int)floorf(fymin);
            bwid = (int)floorf(fxmax) + 2 - xs0;
            bhei = (int)floorf(fymax) + 2 - ys0;
            path = (bwid <= SBW && bhei <= SBH) ? 1 : 2;
        } else {
            path = 2;
        }
    }

    if (path == 1) {
        // ---- cooperative staging (flip folded into source index) ----
        #pragma unroll
        for (int c = 0; c < Cn; c++) {
            const float* ic = images + img_base + (size_t)c * HW;
            float* sc_ = s_img + c * SCH;
            for (int r = warp; r < bhei; r += 8) {
                const int gr = (ys0 + r) * Wn;
                for (int col = lane; col < bwid; col += 32) {
                    const int gxp = (p.flip > 0) ? (Wn - 1 - (xs0 + col)) : (xs0 + col);
                    sc_[r * SBW + col] = ic[gr + gxp];
                }
            }
        }
        __syncthreads();

        #pragma unroll
        for (int k = 0; k < 4; k++) {
            const int x = tx0 + ((warp & 1) << 4) + (lane & 15);
            const int y = ty0 + 8 * k + ((warp >> 1) << 1) + (lane >> 4);
            const size_t oi = img_base + (size_t)y * Wn + x;

            const bool incut = (p.cut > 0) &&
                (y >= p.y0) && (y < p.y0 + CUT_H) &&
                (x >= p.x0) && (x < p.x0 + CUT_W);
            if (incut) {
                out[oi]          = noise[oi];
                out[oi + HW]     = noise[oi + HW];
                out[oi + 2 * HW] = noise[oi + 2 * HW];
                continue;
            }

            const float fx = Ax * (float)x + Bx * (float)y + Cx;
            const float fy = Ay * (float)x + By * (float)y + Cy;
            const float x0f = floorf(fx);
            const float y0f = floorf(fy);
            const float wx = fx - x0f;
            const float wy = fy - y0f;
            const int base = ((int)y0f - ys0) * SBW + ((int)x0f - xs0);

            float r[Cn];
            #pragma unroll
            for (int c = 0; c < Cn; c++) {
                const float* sc_ = s_img + c * SCH + base;
                const float v00 = sc_[0];
                const float v01 = sc_[1];
                const float v10 = sc_[SBW];
                const float v11 = sc_[SBW + 1];
                const float top = v00 + wx * (v01 - v00);
                const float bot = v10 + wx * (v11 - v10);
                r[c] = top + wy * (bot - top);
            }
            color_and_store(r[0], r[1], r[2], p, out, oi);
        }
    } else {
        // ---- scalar gather paths (reflect-safe) ----
        #pragma unroll
        for (int k = 0; k < 4; k++) {
            int x, y;
            if (path == 0) {            // row-major (unrotated)
                x = tx0 + lane;
                y = ty0 + 8 * k + warp;
            } else {                    // 16x2 warp tile (rotated border)
                x = tx0 + ((warp & 1) << 4) + (lane & 15);
                y = ty0 + 8 * k + ((warp >> 1) << 1) + (lane >> 4);
            }
            const size_t oi = img_base + (size_t)y * Wn + x;

            const bool incut = (p.cut > 0) &&
                (y >= p.y0) && (y < p.y0 + CUT_H) &&
                (x >= p.x0) && (x < p.x0 + CUT_W);
            if (incut) {
                out[oi]          = noise[oi];
                out[oi + HW]     = noise[oi + HW];
                out[oi + 2 * HW] = noise[oi + 2 * HW];
                continue;
            }

            float fx = Ax * (float)x + Bx * (float)y + Cx;
            float fy = Ay * (float)x + By * (float)y + Cy;
            fx = reflect_coord(fx, (float)Wn);
            fy = reflect_coord(fy, (float)Hn);

            const float x0f = floorf(fx);
            const float y0f = floorf(fy);
            const float wx = fx - x0f;
            const float wy = fy - y0f;

            int xi0 = (int)x0f;
            int xi1 = min(xi0 + 1, Wn - 1);
            const int yi0 = (int)y0f;
            const int yi1 = min(yi0 + 1, Hn - 1);
            if (p.flip > 0) {
                xi0 = (Wn - 1) - xi0;
                xi1 = (Wn - 1) - xi1;
            }

            const int o00 = yi0 * Wn + xi0;
            const int o01 = yi0 * Wn + xi1;
            const int o10 = yi1 * Wn + xi0;
            const int o11 = yi1 * Wn + xi1;

            float v00[Cn], v01[Cn], v10[Cn], v11[Cn];
            #pragma unroll
            for (int c = 0; c < Cn; c++) {
                const float* ic = images + img_base + (size_t)c * HW;
                v00[c] = __ldg(ic + o00);
                v01[c] = __ldg(ic + o01);
                v10[c] = __ldg(ic + o10);
                v11[c] = __ldg(ic + o11);
            }
            float r[Cn];
            #pragma unroll
            for (int c = 0; c < Cn; c++) {
                const float top = v00[c] + wx * (v01[c] - v00[c]);
                const float bot = v10[c] + wx * (v11[c] - v10[c]);
                r[c] = top + wy * (bot - top);
            }
            color_and_store(r[0], r[1], r[2], p, out, oi);
        }
    }
}

extern "C" void kernel_launch(void* const* d_in, const int* in_sizes, int n_in,
                              void* d_out, int out_size) {
    const float* images     = (const float*)d_in[0];
    const float* u_angle    = (const float*)d_in[1];
    const float* u_scale    = (const float*)d_in[2];
    const float* u_trans    = (const float*)d_in[3];
    const float* u_bright   = (const float*)d_in[4];
    const float* u_contrast = (const float*)d_in[5];
    const float* u_sat      = (const float*)d_in[6];
    const float* noise      = (const float*)d_in[7];
    const int*   m_flip     = (const int*)d_in[8];
    const int*   m_rot      = (const int*)d_in[9];
    const int*   m_scale    = (const int*)d_in[10];
    const int*   m_trans    = (const int*)d_in[11];
    const int*   m_bright   = (const int*)d_in[12];
    const int*   m_contrast = (const int*)d_in[13];
    const int*   m_sat      = (const int*)d_in[14];
    const int*   m_cut      = (const int*)d_in[15];
    const int*   y0         = (const int*)d_in[16];
    const int*   x0         = (const int*)d_in[17];
    float* out = (float*)d_out;

    precompute_params_kernel<<<1, 64>>>(
        u_angle, u_scale, u_trans, u_bright, u_contrast, u_sat,
        m_flip, m_rot, m_scale, m_trans, m_bright, m_contrast,
        m_sat, m_cut, y0, x0);

    dim3 block(256);
    dim3 grid(256, Bn);   // 16x16 tiles of 32x32 per batch
    augment_kernel<<<grid, block>>>(images, noise, out);
}

// round 5
// speedup vs baseline: 1.1821x; 1.1821x over previous
#include <cuda_runtime.h>
#include <math.h>

#define Bn 64
#define Cn 3
#define Hn 512
#define Wn 512
#define HW (Hn * Wn)
#define CUT_H 256
#define CUT_W 256

#define TILE 32            // output tile per block (32x32)
#define SBW 61             // smem tile stride (odd, anti-conflict)
#define SBH 60             // max staged rows
#define SCH (SBH * SBW)    // floats per staged channel

struct __align__(16) BatchParams {
    float m00, m01, m10, m11;
    float tx, ty;
    float bb, cc, ss;
    int   flip, cut, y0, x0;
    int   vec, pad0, pad1, pad2;
};

__device__ BatchParams g_params[Bn];

__global__ void precompute_params_kernel(
    const float* __restrict__ u_angle, const float* __restrict__ u_scale,
    const float* __restrict__ u_trans, const float* __restrict__ u_bright,
    const float* __restrict__ u_contrast, const float* __restrict__ u_sat,
    const int* __restrict__ m_flip, const int* __restrict__ m_rot,
    const int* __restrict__ m_scale, const int* __restrict__ m_trans,
    const int* __restrict__ m_bright, const int* __restrict__ m_contrast,
    const int* __restrict__ m_sat, const int* __restrict__ m_cut,
    const int* __restrict__ y0, const int* __restrict__ x0)
{
    int b = threadIdx.x;
    if (b >= Bn) return;
    const float PI = 3.14159265358979323846f;
    float angle = (m_rot[b] > 0) ? (u_angle[b] * 2.0f - 1.0f) * PI : 0.0f;
    float sc    = (m_scale[b] > 0) ? (u_scale[b] * 2.0f - 1.0f) * 0.2f + 1.0f : 1.0f;
    float tr    = (m_trans[b] > 0) ? (u_trans[b] * 2.0f - 1.0f) * 0.125f : 0.0f;
    float ca = cosf(angle);
    float sa = sinf(angle);
    BatchParams p;
    p.m00 = sc * ca;  p.m01 = -sc * sa;
    p.m10 = sc * sa;  p.m11 =  sc * ca;
    p.tx = tr; p.ty = tr;
    p.bb = (m_bright[b]   > 0) ? u_bright[b] * 0.2f   : 0.0f;
    p.cc = (m_contrast[b] > 0) ? u_contrast[b] + 0.5f : 1.0f;
    p.ss = (m_sat[b]      > 0) ? u_sat[b] * 2.0f      : 1.0f;
    p.flip = m_flip[b];
    p.cut  = m_cut[b];
    p.y0 = y0[b];
    p.x0 = x0[b];
    p.vec = (m_rot[b] > 0) ? 1 : 0;
    g_params[b] = p;
}

__device__ __forceinline__ float reflect_coord(float v, float size) {
    v = fabsf(v + 0.5f);
    v = fmodf(v, 2.0f * size);
    v = fminf(v, 2.0f * size - v);
    return fminf(fmaxf(v - 0.5f, 0.0f), size - 1.0f);
}

__device__ __forceinline__ float clip1(float v) {
    return fminf(fmaxf(v, -1.0f), 1.0f);
}

__device__ __forceinline__ void color_and_store(
    float r0, float r1, float r2, const BatchParams& p,
    float* __restrict__ out, size_t out_idx)
{
    r0 = clip1(clip1(r0 + p.bb) * p.cc);
    r1 = clip1(clip1(r1 + p.bb) * p.cc);
    r2 = clip1(clip1(r2 + p.bb) * p.cc);
    const float gray = (r0 + r1 + r2) * (1.0f / 3.0f);
    r0 = clip1(gray + p.ss * (r0 - gray));
    r1 = clip1(gray + p.ss * (r1 - gray));
    r2 = clip1(gray + p.ss * (r2 - gray));
    out[out_idx]          = r0;
    out[out_idx + HW]     = r1;
    out[out_idx + 2 * HW] = r2;
}

__global__ void __launch_bounds__(256, 8) augment_kernel(
    const float* __restrict__ images,
    const float* __restrict__ noise,
    float* __restrict__ out)
{
    __shared__ float s_img[SCH];   // ONE channel staged at a time (14.6 KB)

    const int b = blockIdx.y;
    const BatchParams p = g_params[b];

    const int bx  = blockIdx.x & 15;
    const int by  = blockIdx.x >> 4;
    const int tx0 = bx * TILE;
    const int ty0 = by * TILE;

    const int tid  = threadIdx.x;
    const int warp = tid >> 5;
    const int lane = tid & 31;

    const size_t img_base = (size_t)b * (Cn * HW);

    // ---- full-cut tile: pure noise copy ----
    if (p.cut > 0 &&
        tx0 >= p.x0 && tx0 + TILE <= p.x0 + CUT_W &&
        ty0 >= p.y0 && ty0 + TILE <= p.y0 + CUT_H) {
        #pragma unroll
        for (int k = 0; k < 4; k++) {
            const int y = ty0 + 8 * k + warp;
            const int x = tx0 + lane;
            const size_t oi = img_base + (size_t)y * Wn + x;
            out[oi]          = noise[oi];
            out[oi + HW]     = noise[oi + HW];
            out[oi + 2 * HW] = noise[oi + 2 * HW];
        }
        return;
    }

    // Affine in pixel coords (flipped-image space when p.flip):
    const float S = 512.0f / 511.0f;
    const float Ax = p.m00 * S, Bx = p.m01 * S;
    const float Cx = (p.tx - p.m00 - p.m01) * 256.0f + 255.5f;
    const float Ay = p.m10 * S, By = p.m11 * S;
    const float Cy = (p.ty - p.m10 - p.m11) * 256.0f + 255.5f;

    // ---- path selection (block-uniform) ----
    int path = 0;            // 0 = scalar row-major, 1 = smem staged, 2 = scalar 16x2
    int xs0 = 0, ys0 = 0, bwid = 0, bhei = 0;
    if (p.vec) {
        const float x0a = (float)tx0, x0b = (float)(tx0 + TILE - 1);
        const float y0a = (float)ty0, y0b = (float)(ty0 + TILE - 1);
        const float fxmin = fminf(Ax * x0a, Ax * x0b) + fminf(Bx * y0a, Bx * y0b) + Cx - 0.01f;
        const float fxmax = fmaxf(Ax * x0a, Ax * x0b) + fmaxf(Bx * y0a, Bx * y0b) + Cx + 0.01f;
        const float fymin = fminf(Ay * x0a, Ay * x0b) + fminf(By * y0a, By * y0b) + Cy - 0.01f;
        const float fymax = fmaxf(Ay * x0a, Ay * x0b) + fmaxf(By * y0a, By * y0b) + Cy + 0.01f;
        if (fxmin >= 0.0f && fxmax < 511.0f && fymin >= 0.0f && fymax < 511.0f) {
            xs0 = (int)floorf(fxmin);
            ys0 = (int)floorf(fymin);
            bwid = (int)floorf(fxmax) + 2 - xs0;
            bhei = (int)floorf(fymax) + 2 - ys0;
            path = (bwid <= SBW && bhei <= SBH) ? 1 : 2;
        } else {
            path = 2;
        }
    }

    if (path == 1) {
        // ---- per-channel staged path, row-major compute mapping ----
        // Geometry once (channel-independent):
        int   basei[4];
        float wxv[4], wyv[4];
        const int x = tx0 + lane;
        #pragma unroll
        for (int k = 0; k < 4; k++) {
            const int y = ty0 + 8 * k + warp;
            const float fx = Ax * (float)x + Bx * (float)y + Cx;
            const float fy = Ay * (float)x + By * (float)y + Cy;
            const float x0f = floorf(fx);
            const float y0f = floorf(fy);
            wxv[k] = fx - x0f;
            wyv[k] = fy - y0f;
            basei[k] = ((int)y0f - ys0) * SBW + ((int)x0f - xs0);
        }

        float r[Cn][4];
        #pragma unroll
        for (int c = 0; c < Cn; c++) {
            if (c) __syncthreads();   // previous channel's sampling done
            const float* ic = images + img_base + (size_t)c * HW;
            for (int rr = warp; rr < bhei; rr += 8) {
                const int gr = (ys0 + rr) * Wn;
                float* dst = s_img + rr * SBW;
                if (p.flip > 0) {
                    const int gx0i = Wn - 1 - xs0;
                    for (int col = lane; col < bwid; col += 32)
                        dst[col] = __ldg(ic + gr + gx0i - col);
                } else {
                    for (int col = lane; col < bwid; col += 32)
                        dst[col] = __ldg(ic + gr + xs0 + col);
                }
            }
            __syncthreads();
            #pragma unroll
            for (int k = 0; k < 4; k++) {
                const float* sp = s_img + basei[k];
                const float v00 = sp[0];
                const float v01 = sp[1];
                const float v10 = sp[SBW];
                const float v11 = sp[SBW + 1];
                const float top = v00 + wxv[k] * (v01 - v00);
                const float bot = v10 + wxv[k] * (v11 - v10);
                r[c][k] = top + wyv[k] * (bot - top);
            }
        }

        #pragma unroll
        for (int k = 0; k < 4; k++) {
            const int y = ty0 + 8 * k + warp;
            const size_t oi = img_base + (size_t)y * Wn + x;
            const bool incut = (p.cut > 0) &&
                (y >= p.y0) && (y < p.y0 + CUT_H) &&
                (x >= p.x0) && (x < p.x0 + CUT_W);
            if (incut) {
                out[oi]          = noise[oi];
                out[oi + HW]     = noise[oi + HW];
                out[oi + 2 * HW] = noise[oi + 2 * HW];
            } else {
                color_and_store(r[0][k], r[1][k], r[2][k], p, out, oi);
            }
        }
    } else {
        // ---- scalar gather paths (reflect-safe) ----
        #pragma unroll
        for (int k = 0; k < 4; k++) {
            int x, y;
            if (path == 0) {            // row-major (unrotated)
                x = tx0 + lane;
                y = ty0 + 8 * k + warp;
            } else {                    // 16x2 warp tile (rotated border)
                x = tx0 + ((warp & 1) << 4) + (lane & 15);
                y = ty0 + 8 * k + ((warp >> 1) << 1) + (lane >> 4);
            }
            const size_t oi = img_base + (size_t)y * Wn + x;

            const bool incut = (p.cut > 0) &&
                (y >= p.y0) && (y < p.y0 + CUT_H) &&
                (x >= p.x0) && (x < p.x0 + CUT_W);
            if (incut) {
                out[oi]          = noise[oi];
                out[oi + HW]     = noise[oi + HW];
                out[oi + 2 * HW] = noise[oi + 2 * HW];
                continue;
            }

            float fx = Ax * (float)x + Bx * (float)y + Cx;
            float fy = Ay * (float)x + By * (float)y + Cy;
            fx = reflect_coord(fx, (float)Wn);
            fy = reflect_coord(fy, (float)Hn);

            const float x0f = floorf(fx);
            const float y0f = floorf(fy);
            const float wx = fx - x0f;
            const float wy = fy - y0f;

            int xi0 = (int)x0f;
            int xi1 = min(xi0 + 1, Wn - 1);
            const int yi0 = (int)y0f;
            const int yi1 = min(yi0 + 1, Hn - 1);
            if (p.flip > 0) {
                xi0 = (Wn - 1) - xi0;
                xi1 = (Wn - 1) - xi1;
            }

            const int o00 = yi0 * Wn + xi0;
            const int o01 = yi0 * Wn + xi1;
            const int o10 = yi1 * Wn + xi0;
            const int o11 = yi1 * Wn + xi1;

            float v00[Cn], v01[Cn], v10[Cn], v11[Cn];
            #pragma unroll
            for (int c = 0; c < Cn; c++) {
                const float* ic = images + img_base + (size_t)c * HW;
                v00[c] = __ldg(ic + o00);
                v01[c] = __ldg(ic + o01);
                v10[c] = __ldg(ic + o10);
                v11[c] = __ldg(ic + o11);
            }
            float r[Cn];
            #pragma unroll
            for (int c = 0; c < Cn; c++) {
                const float top = v00[c] + wx * (v01[c] - v00[c]);
                const float bot = v10[c] + wx * (v11[c] - v10[c]);
                r[c] = top + wy * (bot - top);
            }
            color_and_store(r[0], r[1], r[2], p, out, oi);
        }
    }
}

extern "C" void kernel_launch(void* const* d_in, const int* in_sizes, int n_in,
                              void* d_out, int out_size) {
    const float* images     = (const float*)d_in[0];
    const float* u_angle    = (const float*)d_in[1];
    const float* u_scale    = (const float*)d_in[2];
    const float* u_trans    = (const float*)d_in[3];
    const float* u_bright   = (const float*)d_in[4];
    const float* u_contrast = (const float*)d_in[5];
    const float* u_sat      = (const float*)d_in[6];
    const float* noise      = (const float*)d_in[7];
    const int*   m_flip     = (const int*)d_in[8];
    const int*   m_rot      = (const int*)d_in[9];
    const int*   m_scale    = (const int*)d_in[10];
    const int*   m_trans    = (const int*)d_in[11];
    const int*   m_bright   = (const int*)d_in[12];
    const int*   m_contrast = (const int*)d_in[13];
    const int*   m_sat      = (const int*)d_in[14];
    const int*   m_cut      = (const int*)d_in[15];
    const int*   y0         = (const int*)d_in[16];
    const int*   x0         = (const int*)d_in[17];
    float* out = (float*)d_out;

    precompute_params_kernel<<<1, 64>>>(
        u_angle, u_scale, u_trans, u_bright, u_contrast, u_sat,
        m_flip, m_rot, m_scale, m_trans, m_bright, m_contrast,
        m_sat, m_cut, y0, x0);

    dim3 block(256);
    dim3 grid(256, Bn);   // 16x16 tiles of 32x32 per batch
    augment_kernel<<<grid, block>>>(images, noise, out);
}

// round 6
// speedup vs baseline: 1.4869x; 1.2578x over previous
#include <cuda_runtime.h>
#include <math.h>

#define Bn 64
#define Cn 3
#define Hn 512
#define Wn 512
#define HW (Hn * Wn)
#define CUT_H 256
#define CUT_W 256

#define TILE 16
#define SBH 28             // staged rows
#define SBW 36             // smem row stride (mult of 4, conflict-friendly)
#define SCH (SBH * SBW)    // 1008 floats per channel

struct __align__(16) BatchParams {
    float Ax, Bx, Cx, Ay, By, Cy;   // fx = Ax*x + Bx*y + Cx (flip folded in)
    float bb, cc, ss;
    int   cut, y0, x0;
    int   vec, pad0, pad1, pad2;
};

__device__ BatchParams g_params[Bn];

__global__ void precompute_params_kernel(
    const float* __restrict__ u_angle, const float* __restrict__ u_scale,
    const float* __restrict__ u_trans, const float* __restrict__ u_bright,
    const float* __restrict__ u_contrast, const float* __restrict__ u_sat,
    const int* __restrict__ m_flip, const int* __restrict__ m_rot,
    const int* __restrict__ m_scale, const int* __restrict__ m_trans,
    const int* __restrict__ m_bright, const int* __restrict__ m_contrast,
    const int* __restrict__ m_sat, const int* __restrict__ m_cut,
    const int* __restrict__ y0, const int* __restrict__ x0)
{
    int b = threadIdx.x;
    if (b >= Bn) return;
    const float PI = 3.14159265358979323846f;
    float angle = (m_rot[b] > 0) ? (u_angle[b] * 2.0f - 1.0f) * PI : 0.0f;
    float sc    = (m_scale[b] > 0) ? (u_scale[b] * 2.0f - 1.0f) * 0.2f + 1.0f : 1.0f;
    float tr    = (m_trans[b] > 0) ? (u_trans[b] * 2.0f - 1.0f) * 0.125f : 0.0f;
    float ca = cosf(angle);
    float sa = sinf(angle);
    const float m00 = sc * ca, m01 = -sc * sa;
    const float m10 = sc * sa, m11 =  sc * ca;

    const float S = 512.0f / 511.0f;
    float Ax = m00 * S, Bx = m01 * S;
    float Cx = (tr - m00 - m01) * 256.0f + 255.5f;
    float Ay = m10 * S, By = m11 * S;
    float Cy = (tr - m10 - m11) * 256.0f + 255.5f;

    // Horizontal flip folded via mirror: sampling flipped image at fx equals
    // sampling the original at 511-fx (bilinear-reflect commutes with mirror).
    if (m_flip[b] > 0) {
        Ax = -Ax; Bx = -Bx; Cx = 511.0f - Cx;
    }

    BatchParams p;
    p.Ax = Ax; p.Bx = Bx; p.Cx = Cx;
    p.Ay = Ay; p.By = By; p.Cy = Cy;
    p.bb = (m_bright[b]   > 0) ? u_bright[b] * 0.2f   : 0.0f;
    p.cc = (m_contrast[b] > 0) ? u_contrast[b] + 0.5f : 1.0f;
    p.ss = (m_sat[b]      > 0) ? u_sat[b] * 2.0f      : 1.0f;
    p.cut = m_cut[b];
    p.y0 = y0[b];
    p.x0 = x0[b];
    p.vec = (m_rot[b] > 0) ? 1 : 0;
    p.pad0 = p.pad1 = p.pad2 = 0;
    g_params[b] = p;
}

__device__ __forceinline__ float reflect_coord(float v, float size) {
    v = fabsf(v + 0.5f);
    v = fmodf(v, 2.0f * size);
    v = fminf(v, 2.0f * size - v);
    return fminf(fmaxf(v - 0.5f, 0.0f), size - 1.0f);
}

__device__ __forceinline__ float clip1(float v) {
    return fminf(fmaxf(v, -1.0f), 1.0f);
}

__device__ __forceinline__ void color_and_store(
    float r0, float r1, float r2, const BatchParams& p,
    float* __restrict__ out, size_t out_idx)
{
    r0 = clip1(clip1(r0 + p.bb) * p.cc);
    r1 = clip1(clip1(r1 + p.bb) * p.cc);
    r2 = clip1(clip1(r2 + p.bb) * p.cc);
    const float gray = (r0 + r1 + r2) * (1.0f / 3.0f);
    r0 = clip1(gray + p.ss * (r0 - gray));
    r1 = clip1(gray + p.ss * (r1 - gray));
    r2 = clip1(gray + p.ss * (r2 - gray));
    out[out_idx]          = r0;
    out[out_idx + HW]     = r1;
    out[out_idx + 2 * HW] = r2;
}

__global__ void __launch_bounds__(256, 8) augment_kernel(
    const float* __restrict__ images,
    const float* __restrict__ noise,
    float* __restrict__ out)
{
    __shared__ __align__(16) float s_img[Cn * SCH];   // 12.1 KB

    const int b = blockIdx.y;
    const BatchParams p = g_params[b];

    const int tx0 = (blockIdx.x & 31) << 4;
    const int ty0 = (blockIdx.x >> 5) << 4;

    const int tid  = threadIdx.x;
    const int lane = tid & 31;
    const int warp = tid >> 5;
    const int x = tx0 + (lane & 15);
    const int y = ty0 + (warp << 1) + (lane >> 4);

    const size_t img_base = (size_t)b * (Cn * HW);
    const size_t oi = img_base + (size_t)y * Wn + x;

    // ---- full-cut tile: float4 noise copy ----
    if (p.cut > 0 &&
        tx0 >= p.x0 && tx0 + TILE <= p.x0 + CUT_W &&
        ty0 >= p.y0 && ty0 + TILE <= p.y0 + CUT_H) {
        if (tid < 192) {   // 3ch * 16 rows * 4 float4
            const int ch = tid >> 6;
            const int rem = tid & 63;
            const int r  = rem >> 2;
            const int c4 = rem & 3;
            const size_t a = img_base + (size_t)ch * HW +
                             (size_t)(ty0 + r) * Wn + tx0 + (c4 << 2);
            *(float4*)(out + a) = *(const float4*)(noise + a);
        }
        return;
    }

    const bool incut = (p.cut > 0) &&
        (y >= p.y0) && (y < p.y0 + CUT_H) &&
        (x >= p.x0) && (x < p.x0 + CUT_W);

    // ---- path selection (block-uniform) ----
    int path = 0;                    // 0 = scalar, 1 = staged
    int xa = 0, ys0 = 0;
    if (p.vec) {
        const float xA = (float)tx0, xB = (float)(tx0 + TILE - 1);
        const float yA = (float)ty0, yB = (float)(ty0 + TILE - 1);
        const float fxmin = fminf(p.Ax * xA, p.Ax * xB) + fminf(p.Bx * yA, p.Bx * yB) + p.Cx - 0.01f;
        const float fxmax = fmaxf(p.Ax * xA, p.Ax * xB) + fmaxf(p.Bx * yA, p.Bx * yB) + p.Cx + 0.01f;
        const float fymin = fminf(p.Ay * xA, p.Ay * xB) + fminf(p.By * yA, p.By * yB) + p.Cy - 0.01f;
        const float fymax = fmaxf(p.Ay * xA, p.Ay * xB) + fmaxf(p.By * yA, p.By * yB) + p.Cy + 0.01f;
        if (fxmin >= 0.0f && fxmax < 511.0f && fymin >= 0.0f && fymax < 511.0f) {
            const int xs0 = (int)floorf(fxmin);
            xa  = xs0 & ~3;
            ys0 = (int)floorf(fymin);
            const int wneed = (int)floorf(fxmax) + 1 - xa;
            const int hneed = (int)floorf(fymax) + 1 - ys0;
            if (wneed <= 31 && hneed <= SBH - 1) path = 1;
        }
    }

    if (path == 1) {
        // ---- stage 3 channels x 28 rows x 8 float4 (fixed shape, clamped) ----
        #pragma unroll
        for (int ch = 0; ch < Cn; ch++) {
            if (tid < SBH * 8) {               // 224 active
                const int r  = tid >> 3;
                const int c4 = tid & 7;
                const int gy = min(ys0 + r, Hn - 1);
                const int gx = min(xa + (c4 << 2), Wn - 4);
                const float4 v = *(const float4*)(images + img_base +
                                   (size_t)ch * HW + (size_t)gy * Wn + gx);
                *(float4*)&s_img[ch * SCH + r * SBW + (c4 << 2)] = v;
            }
        }
        __syncthreads();

        if (incut) {
            out[oi]          = noise[oi];
            out[oi + HW]     = noise[oi + HW];
            out[oi + 2 * HW] = noise[oi + 2 * HW];
            return;
        }

        const float fx = p.Ax * (float)x + p.Bx * (float)y + p.Cx;
        const float fy = p.Ay * (float)x + p.By * (float)y + p.Cy;
        const float x0f = floorf(fx);
        const float y0f = floorf(fy);
        const float wx = fx - x0f;
        const float wy = fy - y0f;
        const int base = ((int)y0f - ys0) * SBW + ((int)x0f - xa);

        float r[Cn];
        #pragma unroll
        for (int c = 0; c < Cn; c++) {
            const float* sp = s_img + c * SCH + base;
            const float v00 = sp[0];
            const float v01 = sp[1];
            const float v10 = sp[SBW];
            const float v11 = sp[SBW + 1];
            const float top = v00 + wx * (v01 - v00);
            const float bot = v10 + wx * (v11 - v10);
            r[c] = top + wy * (bot - top);
        }
        color_and_store(r[0], r[1], r[2], p, out, oi);
    } else {
        // ---- scalar reflect-safe gather (borders + unrotated) ----
        if (incut) {
            out[oi]          = noise[oi];
            out[oi + HW]     = noise[oi + HW];
            out[oi + 2 * HW] = noise[oi + 2 * HW];
            return;
        }

        float fx = p.Ax * (float)x + p.Bx * (float)y + p.Cx;
        float fy = p.Ay * (float)x + p.By * (float)y + p.Cy;
        fx = reflect_coord(fx, (float)Wn);
        fy = reflect_coord(fy, (float)Hn);

        const float x0f = floorf(fx);
        const float y0f = floorf(fy);
        const float wx = fx - x0f;
        const float wy = fy - y0f;

        const int xi0 = (int)x0f;
        const int xi1 = min(xi0 + 1, Wn - 1);
        const int yi0 = (int)y0f;
        const int yi1 = min(yi0 + 1, Hn - 1);

        const int o00 = yi0 * Wn + xi0;
        const int o01 = yi0 * Wn + xi1;
        const int o10 = yi1 * Wn + xi0;
        const int o11 = yi1 * Wn + xi1;

        float v00[Cn], v01[Cn], v10[Cn], v11[Cn];
        #pragma unroll
        for (int c = 0; c < Cn; c++) {
            const float* ic = images + img_base + (size_t)c * HW;
            v00[c] = __ldg(ic + o00);
            v01[c] = __ldg(ic + o01);
            v10[c] = __ldg(ic + o10);
            v11[c] = __ldg(ic + o11);
        }
        float r[Cn];
        #pragma unroll
        for (int c = 0; c < Cn; c++) {
            const float top = v00[c] + wx * (v01[c] - v00[c]);
            const float bot = v10[c] + wx * (v11[c] - v10[c]);
            r[c] = top + wy * (bot - top);
        }
        color_and_store(r[0], r[1], r[2], p, out, oi);
    }
}

extern "C" void kernel_launch(void* const* d_in, const int* in_sizes, int n_in,
                              void* d_out, int out_size) {
    const float* images     = (const float*)d_in[0];
    const float* u_angle    = (const float*)d_in[1];
    const float* u_scale    = (const float*)d_in[2];
    const float* u_trans    = (const float*)d_in[3];
    const float* u_bright   = (const float*)d_in[4];
    const float* u_contrast = (const float*)d_in[5];
    const float* u_sat      = (const float*)d_in[6];
    const float* noise      = (const float*)d_in[7];
    const int*   m_flip     = (const int*)d_in[8];
    const int*   m_rot      = (const int*)d_in[9];
    const int*   m_scale    = (const int*)d_in[10];
    const int*   m_trans    = (const int*)d_in[11];
    const int*   m_bright   = (const int*)d_in[12];
    const int*   m_contrast = (const int*)d_in[13];
    const int*   m_sat      = (const int*)d_in[14];
    const int*   m_cut      = (const int*)d_in[15];
    const int*   y0         = (const int*)d_in[16];
    const int*   x0         = (const int*)d_in[17];
    float* out = (float*)d_out;

    precompute_params_kernel<<<1, 64>>>(
        u_angle, u_scale, u_trans, u_bright, u_contrast, u_sat,
        m_flip, m_rot, m_scale, m_trans, m_bright, m_contrast,
        m_sat, m_cut, y0, x0);

    dim3 block(256);
    dim3 grid(1024, Bn);   // 32x32 tiles of 16x16 per batch
    augment_kernel<<<grid, block>>>(images, noise, out);
}

// round 7
// speedup vs baseline: 1.5184x; 1.0212x over previous
#include <cuda_runtime.h>
#include <math.h>

#define Bn 64
#define Cn 3
#define Hn 512
#define Wn 512
#define HW (Hn * Wn)
#define CUT_H 256
#define CUT_W 256

#define TILE 16
#define SBH 29             // max staged rows (worst bbox 28 + margin)
#define SBW 36             // smem row stride (mult of 4)
#define SCH (SBH * SBW)

struct __align__(16) BatchParams {
    float Ax, Bx, Cx, Ay, By, Cy;   // fx = Ax*x + Bx*y + Cx (flip folded in)
    float bb, cc, ss;
    int   cut, y0, x0;
    int   vec, pad0, pad1, pad2;
};

__device__ BatchParams g_params[Bn];

__global__ void precompute_params_kernel(
    const float* __restrict__ u_angle, const float* __restrict__ u_scale,
    const float* __restrict__ u_trans, const float* __restrict__ u_bright,
    const float* __restrict__ u_contrast, const float* __restrict__ u_sat,
    const int* __restrict__ m_flip, const int* __restrict__ m_rot,
    const int* __restrict__ m_scale, const int* __restrict__ m_trans,
    const int* __restrict__ m_bright, const int* __restrict__ m_contrast,
    const int* __restrict__ m_sat, const int* __restrict__ m_cut,
    const int* __restrict__ y0, const int* __restrict__ x0)
{
    int b = threadIdx.x;
    if (b >= Bn) return;
    const float PI = 3.14159265358979323846f;
    float angle = (m_rot[b] > 0) ? (u_angle[b] * 2.0f - 1.0f) * PI : 0.0f;
    float sc    = (m_scale[b] > 0) ? (u_scale[b] * 2.0f - 1.0f) * 0.2f + 1.0f : 1.0f;
    float tr    = (m_trans[b] > 0) ? (u_trans[b] * 2.0f - 1.0f) * 0.125f : 0.0f;
    float ca = cosf(angle);
    float sa = sinf(angle);
    const float m00 = sc * ca, m01 = -sc * sa;
    const float m10 = sc * sa, m11 =  sc * ca;

    const float S = 512.0f / 511.0f;
    float Ax = m00 * S, Bx = m01 * S;
    float Cx = (tr - m00 - m01) * 256.0f + 255.5f;
    float Ay = m10 * S, By = m11 * S;
    float Cy = (tr - m10 - m11) * 256.0f + 255.5f;

    // Flip folded via mirror: bilinear-reflect commutes with x -> 511-x.
    if (m_flip[b] > 0) {
        Ax = -Ax; Bx = -Bx; Cx = 511.0f - Cx;
    }

    BatchParams p;
    p.Ax = Ax; p.Bx = Bx; p.Cx = Cx;
    p.Ay = Ay; p.By = By; p.Cy = Cy;
    p.bb = (m_bright[b]   > 0) ? u_bright[b] * 0.2f   : 0.0f;
    p.cc = (m_contrast[b] > 0) ? u_contrast[b] + 0.5f : 1.0f;
    p.ss = (m_sat[b]      > 0) ? u_sat[b] * 2.0f      : 1.0f;
    p.cut = m_cut[b];
    p.y0 = y0[b];
    p.x0 = x0[b];
    p.vec = (m_rot[b] > 0) ? 1 : 0;
    p.pad0 = p.pad1 = p.pad2 = 0;
    g_params[b] = p;
}

__device__ __forceinline__ float reflect_coord(float v, float size) {
    v = fabsf(v + 0.5f);
    v = fmodf(v, 2.0f * size);
    v = fminf(v, 2.0f * size - v);
    return fminf(fmaxf(v - 0.5f, 0.0f), size - 1.0f);
}

// Covering interval of reflect([a,b]) for ranges much narrower than 512
// (at most one fold per side; reflect is piecewise monotonic).
__device__ __forceinline__ void reflect_range(float a, float b,
                                              float& lo, float& hi) {
    const float ra = reflect_coord(a, 512.0f);
    const float rb = reflect_coord(b, 512.0f);
    lo = fminf(ra, rb);
    hi = fmaxf(ra, rb);
    if (a < -0.5f && b > -0.5f)   lo = 0.0f;    // low fold extremum
    if (a < 511.5f && b > 511.5f) hi = 511.0f;  // high fold extremum
}

__device__ __forceinline__ float clip1(float v) {
    return fminf(fmaxf(v, -1.0f), 1.0f);
}

__device__ __forceinline__ void color_and_store(
    float r0, float r1, float r2, const BatchParams& p,
    float* __restrict__ out, size_t out_idx)
{
    r0 = clip1(clip1(r0 + p.bb) * p.cc);
    r1 = clip1(clip1(r1 + p.bb) * p.cc);
    r2 = clip1(clip1(r2 + p.bb) * p.cc);
    const float gray = (r0 + r1 + r2) * (1.0f / 3.0f);
    r0 = clip1(gray + p.ss * (r0 - gray));
    r1 = clip1(gray + p.ss * (r1 - gray));
    r2 = clip1(gray + p.ss * (r2 - gray));
    out[out_idx]          = r0;
    out[out_idx + HW]     = r1;
    out[out_idx + 2 * HW] = r2;
}

__global__ void __launch_bounds__(256, 8) augment_kernel(
    const float* __restrict__ images,
    const float* __restrict__ noise,
    float* __restrict__ out)
{
    __shared__ __align__(16) float s_img[Cn * SCH];   // 12.5 KB

    const int b = blockIdx.y;
    const BatchParams p = g_params[b];

    const int tx0 = (blockIdx.x & 31) << 4;
    const int ty0 = (blockIdx.x >> 5) << 4;

    const int tid  = threadIdx.x;
    const int lane = tid & 31;
    const int warp = tid >> 5;
    const int x = tx0 + (lane & 15);
    const int y = ty0 + (warp << 1) + (lane >> 4);

    const size_t img_base = (size_t)b * (Cn * HW);
    const size_t oi = img_base + (size_t)y * Wn + x;

    // ---- full-cut tile: float4 noise copy ----
    if (p.cut > 0 &&
        tx0 >= p.x0 && tx0 + TILE <= p.x0 + CUT_W &&
        ty0 >= p.y0 && ty0 + TILE <= p.y0 + CUT_H) {
        if (tid < 192) {
            const int ch = tid >> 6;
            const int rem = tid & 63;
            const int r  = rem >> 2;
            const int c4 = rem & 3;
            const size_t a = img_base + (size_t)ch * HW +
                             (size_t)(ty0 + r) * Wn + tx0 + (c4 << 2);
            *(float4*)(out + a) = *(const float4*)(noise + a);
        }
        return;
    }

    const bool incut = (p.cut > 0) &&
        (y >= p.y0) && (y < p.y0 + CUT_H) &&
        (x >= p.x0) && (x < p.x0 + CUT_W);

    if (p.vec) {
        // ================= staged path: ALL rotated tiles =================
        // Raw source bbox of the tile (corner extremes of the affine map).
        const float xA = (float)tx0, xB = (float)(tx0 + TILE - 1);
        const float yA = (float)ty0, yB = (float)(ty0 + TILE - 1);
        const float rxa = fminf(p.Ax * xA, p.Ax * xB) + fminf(p.Bx * yA, p.Bx * yB) + p.Cx - 0.01f;
        const float rxb = fmaxf(p.Ax * xA, p.Ax * xB) + fmaxf(p.Bx * yA, p.Bx * yB) + p.Cx + 0.01f;
        const float rya = fminf(p.Ay * xA, p.Ay * xB) + fminf(p.By * yA, p.By * yB) + p.Cy - 0.01f;
        const float ryb = fmaxf(p.Ay * xA, p.Ay * xB) + fmaxf(p.By * yA, p.By * yB) + p.Cy + 0.01f;

        const bool interior = (rxa >= 0.0f && rxb < 511.0f &&
                               rya >= 0.0f && ryb < 511.0f);

        float lox, hix, loy, hiy;
        reflect_range(rxa, rxb, lox, hix);
        reflect_range(rya, ryb, loy, hiy);

        const int xa   = ((int)floorf(lox)) & ~3;
        const int ys0  = (int)floorf(loy);
        const int rows = min((int)floorf(hiy) + 2 - ys0, SBH);

        // ---- stage: 3 ch x rows x 8 float4, cols clamped (all slots finite) ----
        if (tid < (rows << 3)) {
            const int r  = tid >> 3;
            const int c4 = tid & 7;
            const int gy = min(ys0 + r, Hn - 1);
            const int gx = min(xa + (c4 << 2), Wn - 4);
            const size_t ga = img_base + (size_t)gy * Wn + gx;
            const int    sa = r * SBW + (c4 << 2);
            *(float4*)&s_img[sa]           = *(const float4*)(images + ga);
            *(float4*)&s_img[SCH + sa]     = *(const float4*)(images + ga + HW);
            *(float4*)&s_img[2 * SCH + sa] = *(const float4*)(images + ga + 2 * HW);
        }
        __syncthreads();

        if (incut) {
            out[oi]          = noise[oi];
            out[oi + HW]     = noise[oi + HW];
            out[oi + 2 * HW] = noise[oi + 2 * HW];
            return;
        }

        float fx = p.Ax * (float)x + p.Bx * (float)y + p.Cx;
        float fy = p.Ay * (float)x + p.By * (float)y + p.Cy;
        if (!interior) {            // block-uniform
            fx = reflect_coord(fx, (float)Wn);
            fy = reflect_coord(fy, (float)Hn);
        }
        const float x0f = floorf(fx);
        const float y0f = floorf(fy);
        const float wx = fx - x0f;
        const float wy = fy - y0f;
        const int base = ((int)y0f - ys0) * SBW + ((int)x0f - xa);

        float r[Cn];
        #pragma unroll
        for (int c = 0; c < Cn; c++) {
            const float* sp = s_img + c * SCH + base;
            const float v00 = sp[0];
            const float v01 = sp[1];
            const float v10 = sp[SBW];
            const float v11 = sp[SBW + 1];
            const float top = v00 + wx * (v01 - v00);
            const float bot = v10 + wx * (v11 - v10);
            r[c] = top + wy * (bot - top);
        }
        color_and_store(r[0], r[1], r[2], p, out, oi);
    } else {
        // ================= scalar path: unrotated batches =================
        if (incut) {
            out[oi]          = noise[oi];
            out[oi + HW]     = noise[oi + HW];
            out[oi + 2 * HW] = noise[oi + 2 * HW];
            return;
        }

        float fx = p.Ax * (float)x + p.Bx * (float)y + p.Cx;
        float fy = p.Ay * (float)x + p.By * (float)y + p.Cy;
        fx = reflect_coord(fx, (float)Wn);
        fy = reflect_coord(fy, (float)Hn);

        const float x0f = floorf(fx);
        const float y0f = floorf(fy);
        const float wx = fx - x0f;
        const float wy = fy - y0f;

        const int xi0 = (int)x0f;
        const int xi1 = min(xi0 + 1, Wn - 1);
        const int yi0 = (int)y0f;
        const int yi1 = min(yi0 + 1, Hn - 1);

        const int o00 = yi0 * Wn + xi0;
        const int o01 = yi0 * Wn + xi1;
        const int o10 = yi1 * Wn + xi0;
        const int o11 = yi1 * Wn + xi1;

        float v00[Cn], v01[Cn], v10[Cn], v11[Cn];
        #pragma unroll
        for (int c = 0; c < Cn; c++) {
            const float* ic = images + img_base + (size_t)c * HW;
            v00[c] = __ldg(ic + o00);
            v01[c] = __ldg(ic + o01);
            v10[c] = __ldg(ic + o10);
            v11[c] = __ldg(ic + o11);
        }
        float r[Cn];
        #pragma unroll
        for (int c = 0; c < Cn; c++) {
            const float top = v00[c] + wx * (v01[c] - v00[c]);
            const float bot = v10[c] + wx * (v11[c] - v10[c]);
            r[c] = top + wy * (bot - top);
        }
        color_and_store(r[0], r[1], r[2], p, out, oi);
    }
}

extern "C" void kernel_launch(void* const* d_in, const int* in_sizes, int n_in,
                              void* d_out, int out_size) {
    const float* images     = (const float*)d_in[0];
    const float* u_angle    = (const float*)d_in[1];
    const float* u_scale    = (const float*)d_in[2];
    const float* u_trans    = (const float*)d_in[3];
    const float* u_bright   = (const float*)d_in[4];
    const float* u_contrast = (const float*)d_in[5];
    const float* u_sat      = (const float*)d_in[6];
    const float* noise      = (const float*)d_in[7];
    const int*   m_flip     = (const int*)d_in[8];
    const int*   m_rot      = (const int*)d_in[9];
    const int*   m_scale    = (const int*)d_in[10];
    const int*   m_trans    = (const int*)d_in[11];
    const int*   m_bright   = (const int*)d_in[12];
    const int*   m_contrast = (const int*)d_in[13];
    const int*   m_sat      = (const int*)d_in[14];
    const int*   m_cut      = (const int*)d_in[15];
    const int*   y0         = (const int*)d_in[16];
    const int*   x0         = (const int*)d_in[17];
    float* out = (float*)d_out;

    precompute_params_kernel<<<1, 64>>>(
        u_angle, u_scale, u_trans, u_bright, u_contrast, u_sat,
        m_flip, m_rot, m_scale, m_trans, m_bright, m_contrast,
        m_sat, m_cut, y0, x0);

    dim3 block(256);
    dim3 grid(1024, Bn);   // 32x32 tiles of 16x16 per batch
    augment_kernel<<<grid, block>>>(images, noise, out);
}